// round 1
// baseline (speedup 1.0000x reference)
#include <cuda_runtime.h>
#include <cstdint>
#include <cstddef>

#define NN 4096
#define IN_DIM 256
#define HID 64
#define OUT_DIM 128
#define NHEAD 4
#define NW (NN/32)      // 128 bitmask words per row
#define S1 2            // j-splits, layer 1  -> 16*4*2 = 128 CTAs
#define S2 8            // j-splits, layer 2  -> 16*1*8 = 128 CTAs

// ----- scratch (static device globals; no allocation allowed) -----
__device__ uint32_t g_adjT[(size_t)NW * NN];                 // 2 MB, word-major bitmask
__device__ float g_h1[(size_t)NHEAD * NN * HID];             // 4 MB  layer-1 projected feats
__device__ float g_src1[NHEAD * NN], g_dst1[NHEAD * NN], g_m1[NHEAD * NN];
__device__ float g_hcat[(size_t)NN * (NHEAD * HID)];         // 4 MB  ELU'd concat
__device__ float g_h2[(size_t)NN * OUT_DIM];                 // 2 MB  layer-2 projected feats
__device__ float g_src2[NN], g_dst2[NN], g_m2[NN];
__device__ float g_part1[(size_t)S1 * NHEAD * NN * HID];     // 8 MB  split partials
__device__ float g_l1[S1 * NHEAD * NN];
__device__ float g_part2[(size_t)S2 * NN * OUT_DIM];         // 16 MB
__device__ float g_l2[S2 * NN];

__device__ __forceinline__ float lrelu(float x) { return x > 0.f ? x : 0.2f * x; }

// ---------------------------------------------------------------------------
// 1) Pack adjacency int32 [N,N] -> transposed bitmask [NW][N] (coalesced reads
//    of a column of words later). One warp per output word.
// ---------------------------------------------------------------------------
__global__ void pack_adj_kernel(const int* __restrict__ adj) {
    int gw   = (blockIdx.x * blockDim.x + threadIdx.x) >> 5;   // global warp id
    int lane = threadIdx.x & 31;
    int row = gw >> 7;            // NW = 128 words per row
    int w   = gw & (NW - 1);
    int v = adj[(size_t)row * NN + (w << 5) + lane];
    unsigned m = __ballot_sync(0xffffffffu, v > 0);
    if (lane == 0) g_adjT[(size_t)w * NN + row] = m;
}

// ---------------------------------------------------------------------------
// 2) Projection GEMM: C[M x Nc] = A[M x 256] @ B[256 x Nc] per head (grid.z).
//    64x64 C tile / CTA, 16-wide K tiles, 4x4 micro-tile per thread.
// ---------------------------------------------------------------------------
template <int LAYER>
__global__ void __launch_bounds__(256) gemm_kernel(const float* __restrict__ Ain,
                                                   const float* __restrict__ Bin) {
    constexpr int K  = IN_DIM;                       // 256 for both layers
    constexpr int Nc = (LAYER == 1) ? HID : OUT_DIM;
    const float* A = (LAYER == 1) ? Ain : g_hcat;
    const float* B = Bin + (size_t)blockIdx.z * ((LAYER == 1) ? (size_t)IN_DIM * HID : 0);
    float* C = ((LAYER == 1) ? g_h1 : g_h2) + (size_t)blockIdx.z * NN * HID;

    __shared__ float As[16][66];   // [k][row], padded
    __shared__ float Bs[16][64];   // [k][col]

    int row0 = blockIdx.y * 64, col0 = blockIdx.x * 64;
    int tx = threadIdx.x & 15, ty = threadIdx.x >> 4;
    float acc[4][4] = {};

    for (int k0 = 0; k0 < K; k0 += 16) {
        for (int t = threadIdx.x; t < 64 * 16; t += 256) {
            int r = t >> 4, c = t & 15;
            As[c][r] = A[(size_t)(row0 + r) * K + k0 + c];
        }
        for (int t = threadIdx.x; t < 16 * 64; t += 256) {
            int r = t >> 6, c = t & 63;
            Bs[r][c] = B[(size_t)(k0 + r) * Nc + col0 + c];
        }
        __syncthreads();
#pragma unroll
        for (int kk = 0; kk < 16; kk++) {
            float av[4], bv[4];
#pragma unroll
            for (int u = 0; u < 4; u++) av[u] = As[kk][ty * 4 + u];
#pragma unroll
            for (int v = 0; v < 4; v++) bv[v] = Bs[kk][tx * 4 + v];
#pragma unroll
            for (int u = 0; u < 4; u++)
#pragma unroll
                for (int v = 0; v < 4; v++) acc[u][v] = fmaf(av[u], bv[v], acc[u][v]);
        }
        __syncthreads();
    }
#pragma unroll
    for (int u = 0; u < 4; u++)
#pragma unroll
        for (int v = 0; v < 4; v++)
            C[(size_t)(row0 + ty * 4 + u) * Nc + col0 + tx * 4 + v] = acc[u][v];
}

// ---------------------------------------------------------------------------
// 3) src/dst scalars: src_i = h_i . a[:F], dst_i = h_i . a[F:]. Warp per row.
// ---------------------------------------------------------------------------
template <int LAYER>
__global__ void srcdst_kernel(const float* __restrict__ avec) {
    constexpr int F = (LAYER == 1) ? HID : OUT_DIM;
    const float* feat = (LAYER == 1) ? g_h1 : g_h2;
    float* srcv = (LAYER == 1) ? g_src1 : g_src2;
    float* dstv = (LAYER == 1) ? g_dst1 : g_dst2;

    int h = blockIdx.y;
    int wid = threadIdx.x >> 5, lane = threadIdx.x & 31;
    int i = blockIdx.x * 8 + wid;
    const float* fr = feat + ((size_t)h * NN + i) * F;
    const float* a = avec + (size_t)h * 2 * F;
    float s = 0.f, d = 0.f;
#pragma unroll
    for (int c = lane; c < F; c += 32) {
        float v = fr[c];
        s = fmaf(v, a[c], s);
        d = fmaf(v, a[F + c], d);
    }
#pragma unroll
    for (int o = 16; o > 0; o >>= 1) {
        s += __shfl_xor_sync(0xffffffffu, s, o);
        d += __shfl_xor_sync(0xffffffffu, d, o);
    }
    if (lane == 0) { srcv[h * NN + i] = s; dstv[h * NN + i] = d; }
}

// ---------------------------------------------------------------------------
// 4) Exact softmax row-max: m_i = max_{j in nbr(i)} dst_j (leakyrelu is
//    monotone so row max of e is lrelu(src_i + m_i)). Thread per row.
// ---------------------------------------------------------------------------
template <int LAYER>
__global__ void __launch_bounds__(256) maxdst_kernel() {
    const float* dstv = (LAYER == 1) ? g_dst1 : g_dst2;
    float* mv = (LAYER == 1) ? g_m1 : g_m2;
    __shared__ float sd[NN];      // 16 KB
    int h = blockIdx.y;
    for (int t = threadIdx.x; t < NN; t += 256) sd[t] = dstv[h * NN + t];
    __syncthreads();
    int i = blockIdx.x * 256 + threadIdx.x;
    float md = -3.0e38f;
    for (int w = 0; w < NW; w++) {
        uint32_t bits = g_adjT[(size_t)w * NN + i];
        while (bits) {
            int b = __ffs(bits) - 1;
            bits &= bits - 1;
            md = fmaxf(md, sd[(w << 5) + b]);
        }
    }
    mv[h * NN + i] = md;
}

// ---------------------------------------------------------------------------
// 5) Attention: thread per row (256 rows/CTA), j split across grid.z.
//    Exact max known -> single pass, additive partials, no atomics.
// ---------------------------------------------------------------------------
template <int LAYER>
__global__ void __launch_bounds__(256, 1) attn_kernel() {
    constexpr int F  = (LAYER == 1) ? HID : OUT_DIM;
    constexpr int NS = (LAYER == 1) ? S1 : S2;
    constexpr int TJ = 64;
    constexpr int NH = (LAYER == 1) ? NHEAD : 1;
    const float* Vall = (LAYER == 1) ? g_h1 : g_h2;
    const float* srcv = (LAYER == 1) ? g_src1 : g_src2;
    const float* dstv = (LAYER == 1) ? g_dst1 : g_dst2;
    const float* mv   = (LAYER == 1) ? g_m1 : g_m2;
    float* part = (LAYER == 1) ? g_part1 : g_part2;
    float* lout = (LAYER == 1) ? g_l1 : g_l2;

    __shared__ __align__(16) float sV[TJ * F];
    __shared__ float sD[TJ];

    int h = blockIdx.y, s = blockIdx.z;
    int i = blockIdx.x * 256 + threadIdx.x;
    const float* V = Vall + (size_t)h * NN * F;
    float srci = srcv[h * NN + i];
    float mi = lrelu(srci + mv[h * NN + i]);

    float4 acc[F / 4];
#pragma unroll
    for (int f = 0; f < F / 4; f++) acc[f] = make_float4(0.f, 0.f, 0.f, 0.f);
    float l = 0.f;

    const int jspan = NN / NS;
    const int j0 = s * jspan;
    for (int jt = j0; jt < j0 + jspan; jt += TJ) {
        __syncthreads();
        const float4* gv = (const float4*)(V + (size_t)jt * F);
        float4* sv4 = (float4*)sV;
        for (int t = threadIdx.x; t < TJ * F / 4; t += 256) sv4[t] = gv[t];
        if (threadIdx.x < TJ) sD[threadIdx.x] = dstv[h * NN + jt + threadIdx.x];
        __syncthreads();

        unsigned long long bits =
            (unsigned long long)g_adjT[(size_t)(jt >> 5) * NN + i] |
            ((unsigned long long)g_adjT[(size_t)((jt >> 5) + 1) * NN + i] << 32);

#pragma unroll 1
        for (int jj = 0; jj < TJ; jj++) {
            float p = 0.f;
            if (bits & 1ull) p = __expf(lrelu(srci + sD[jj]) - mi);
            bits >>= 1;
            l += p;
            const float4* vr = (const float4*)(sV + jj * F);
#pragma unroll
            for (int f = 0; f < F / 4; f++) {
                float4 v = vr[f];
                acc[f].x = fmaf(p, v.x, acc[f].x);
                acc[f].y = fmaf(p, v.y, acc[f].y);
                acc[f].z = fmaf(p, v.z, acc[f].z);
                acc[f].w = fmaf(p, v.w, acc[f].w);
            }
        }
    }

    float4* po = (float4*)(part + (((size_t)s * NH + h) * NN + i) * F);
#pragma unroll
    for (int f = 0; f < F / 4; f++) po[f] = acc[f];
    lout[((size_t)s * NH + h) * NN + i] = l;
}

// ---------------------------------------------------------------------------
// 6) Reduce splits, divide by l, (layer 1: ELU), write to hcat / output.
// ---------------------------------------------------------------------------
template <int LAYER>
__global__ void finalize_kernel(float* __restrict__ outp) {
    constexpr int F  = (LAYER == 1) ? HID : OUT_DIM;
    constexpr int NS = (LAYER == 1) ? S1 : S2;
    constexpr int NH = (LAYER == 1) ? NHEAD : 1;
    const float* part = (LAYER == 1) ? g_part1 : g_part2;
    const float* lsum = (LAYER == 1) ? g_l1 : g_l2;

    int idx = blockIdx.x * 256 + threadIdx.x;          // over NH*NN*F
    int f = idx % F;
    int i = (idx / F) % NN;
    int h = idx / (F * NN);
    float a = 0.f, L = 0.f;
#pragma unroll
    for (int s = 0; s < NS; s++) {
        a += part[(((size_t)s * NH + h) * NN + i) * F + f];
        L += lsum[((size_t)s * NH + h) * NN + i];
    }
    float v = a / L;
    if (LAYER == 1) {
        v = v > 0.f ? v : expm1f(v);
        g_hcat[(size_t)i * (NHEAD * HID) + h * HID + f] = v;
    } else {
        outp[(size_t)i * OUT_DIM + f] = v;
    }
}

// ---------------------------------------------------------------------------
extern "C" void kernel_launch(void* const* d_in, const int* in_sizes, int n_in,
                              void* d_out, int out_size) {
    const float* x   = (const float*)d_in[0];   // [4096,256]
    const int*   adj = (const int*)d_in[1];     // [4096,4096]
    const float* W1  = (const float*)d_in[2];   // [4,256,64]
    const float* a1  = (const float*)d_in[3];   // [4,128]
    const float* W2  = (const float*)d_in[4];   // [256,128]
    const float* a2  = (const float*)d_in[5];   // [256]
    float* out = (float*)d_out;                 // [4096,128]

    // bitmask pack (once, 64MB -> 2MB)
    pack_adj_kernel<<<(size_t)NN * NW / 8, 256>>>(adj);

    // ---- layer 1 ----
    gemm_kernel<1><<<dim3(1, NN / 64, NHEAD), 256>>>(x, W1);
    srcdst_kernel<1><<<dim3(NN / 8, NHEAD), 256>>>(a1);
    maxdst_kernel<1><<<dim3(NN / 256, NHEAD), 256>>>();
    attn_kernel<1><<<dim3(NN / 256, NHEAD, S1), 256>>>();
    finalize_kernel<1><<<NHEAD * NN * HID / 256, 256>>>(nullptr);

    // ---- layer 2 ----
    gemm_kernel<2><<<dim3(OUT_DIM / 64, NN / 64, 1), 256>>>(nullptr, W2);
    srcdst_kernel<2><<<dim3(NN / 8, 1), 256>>>(a2);
    maxdst_kernel<2><<<dim3(NN / 256, 1), 256>>>();
    attn_kernel<2><<<dim3(NN / 256, 1, S2), 256>>>();
    finalize_kernel<2><<<NN * OUT_DIM / 256, 256>>>(out);
}

// round 2
// speedup vs baseline: 1.5636x; 1.5636x over previous
#include <cuda_runtime.h>
#include <cstdint>
#include <cstddef>

#define NN 4096
#define IN_DIM 256
#define HID 64
#define OUT_DIM 128
#define NHEAD 4
#define NW (NN/32)      // 128 bitmask words per row
#define S1 4            // j-splits, layer 1  -> 16*4*4 = 256 CTAs (256 thr)
#define S2 8            // j-splits, layer 2  -> 32*1*8 = 256 CTAs (128 thr)

// ----- scratch (static device globals; no allocation allowed) -----
__device__ uint32_t g_adjT[(size_t)NW * NN];                 // 2 MB, word-major bitmask
__device__ float g_h1[(size_t)NHEAD * NN * HID];             // 4 MB  layer-1 projected feats
__device__ float g_src1[NHEAD * NN], g_dst1[NHEAD * NN];
__device__ float g_hcat[(size_t)NN * (NHEAD * HID)];         // 4 MB  ELU'd concat
__device__ float g_h2[(size_t)NN * OUT_DIM];                 // 2 MB  layer-2 projected feats
__device__ float g_src2[NN], g_dst2[NN];
__device__ float g_gm1[NHEAD], g_gm2[1];                     // global dst max per head
__device__ float g_part1[(size_t)S1 * NHEAD * NN * HID];     // 16 MB split partials
__device__ float g_l1[S1 * NHEAD * NN];
__device__ float g_part2[(size_t)S2 * NN * OUT_DIM];         // 16 MB
__device__ float g_l2[S2 * NN];

__device__ __forceinline__ float lrelu(float x) { return x > 0.f ? x : 0.2f * x; }

// ---------------------------------------------------------------------------
// 1) Pack adjacency int32 [N,N] -> transposed bitmask [NW][N].
// ---------------------------------------------------------------------------
__global__ void pack_adj_kernel(const int* __restrict__ adj) {
    int gw   = (blockIdx.x * blockDim.x + threadIdx.x) >> 5;
    int lane = threadIdx.x & 31;
    int row = gw >> 7;
    int w   = gw & (NW - 1);
    int v = adj[(size_t)row * NN + (w << 5) + lane];
    unsigned m = __ballot_sync(0xffffffffu, v > 0);
    if (lane == 0) g_adjT[(size_t)w * NN + row] = m;
}

// ---------------------------------------------------------------------------
// 2) Projection GEMM: C[M x Nc] = A[M x 256] @ B[256 x Nc] per head (grid.z).
// ---------------------------------------------------------------------------
template <int LAYER>
__global__ void __launch_bounds__(256) gemm_kernel(const float* __restrict__ Ain,
                                                   const float* __restrict__ Bin) {
    constexpr int K  = IN_DIM;
    constexpr int Nc = (LAYER == 1) ? HID : OUT_DIM;
    const float* A = (LAYER == 1) ? Ain : g_hcat;
    const float* B = Bin + (size_t)blockIdx.z * ((LAYER == 1) ? (size_t)IN_DIM * HID : 0);
    float* C = ((LAYER == 1) ? g_h1 : g_h2) + (size_t)blockIdx.z * NN * HID;

    __shared__ float As[16][66];
    __shared__ float Bs[16][64];

    int row0 = blockIdx.y * 64, col0 = blockIdx.x * 64;
    int tx = threadIdx.x & 15, ty = threadIdx.x >> 4;
    float acc[4][4] = {};

    for (int k0 = 0; k0 < K; k0 += 16) {
        for (int t = threadIdx.x; t < 64 * 16; t += 256) {
            int r = t >> 4, c = t & 15;
            As[c][r] = A[(size_t)(row0 + r) * K + k0 + c];
        }
        for (int t = threadIdx.x; t < 16 * 64; t += 256) {
            int r = t >> 6, c = t & 63;
            Bs[r][c] = B[(size_t)(k0 + r) * Nc + col0 + c];
        }
        __syncthreads();
#pragma unroll
        for (int kk = 0; kk < 16; kk++) {
            float av[4], bv[4];
#pragma unroll
            for (int u = 0; u < 4; u++) av[u] = As[kk][ty * 4 + u];
#pragma unroll
            for (int v = 0; v < 4; v++) bv[v] = Bs[kk][tx * 4 + v];
#pragma unroll
            for (int u = 0; u < 4; u++)
#pragma unroll
                for (int v = 0; v < 4; v++) acc[u][v] = fmaf(av[u], bv[v], acc[u][v]);
        }
        __syncthreads();
    }
#pragma unroll
    for (int u = 0; u < 4; u++)
#pragma unroll
        for (int v = 0; v < 4; v++)
            C[(size_t)(row0 + ty * 4 + u) * Nc + col0 + tx * 4 + v] = acc[u][v];
}

// ---------------------------------------------------------------------------
// 3) src/dst scalars. Warp per row.
// ---------------------------------------------------------------------------
template <int LAYER>
__global__ void srcdst_kernel(const float* __restrict__ avec) {
    constexpr int F = (LAYER == 1) ? HID : OUT_DIM;
    const float* feat = (LAYER == 1) ? g_h1 : g_h2;
    float* srcv = (LAYER == 1) ? g_src1 : g_src2;
    float* dstv = (LAYER == 1) ? g_dst1 : g_dst2;

    int h = blockIdx.y;
    int wid = threadIdx.x >> 5, lane = threadIdx.x & 31;
    int i = blockIdx.x * 8 + wid;
    const float* fr = feat + ((size_t)h * NN + i) * F;
    const float* a = avec + (size_t)h * 2 * F;
    float s = 0.f, d = 0.f;
#pragma unroll
    for (int c = lane; c < F; c += 32) {
        float v = fr[c];
        s = fmaf(v, a[c], s);
        d = fmaf(v, a[F + c], d);
    }
#pragma unroll
    for (int o = 16; o > 0; o >>= 1) {
        s += __shfl_xor_sync(0xffffffffu, s, o);
        d += __shfl_xor_sync(0xffffffffu, d, o);
    }
    if (lane == 0) { srcv[h * NN + i] = s; dstv[h * NN + i] = d; }
}

// ---------------------------------------------------------------------------
// 4) Global dst max per head (valid softmax shift: lrelu monotone =>
//    lrelu(src_i + gmax) >= every masked logit; softmax is shift-exact).
// ---------------------------------------------------------------------------
template <int LAYER>
__global__ void gmax_kernel() {
    const float* dstv = (LAYER == 1) ? g_dst1 : g_dst2;
    float* gm = (LAYER == 1) ? g_gm1 : g_gm2;
    __shared__ float red[256];
    int h = blockIdx.x;
    float m = -3.0e38f;
    for (int t = threadIdx.x; t < NN; t += 256) m = fmaxf(m, dstv[h * NN + t]);
    red[threadIdx.x] = m;
    __syncthreads();
    for (int o = 128; o > 0; o >>= 1) {
        if (threadIdx.x < o) red[threadIdx.x] = fmaxf(red[threadIdx.x], red[threadIdx.x + o]);
        __syncthreads();
    }
    if (threadIdx.x == 0) gm[h] = red[0];
}

// ---------------------------------------------------------------------------
// 5) Attention: thread per row (BLK rows/CTA), j split across grid.z.
//    Upper-bound max known -> single pass, additive partials, no atomics.
// ---------------------------------------------------------------------------
template <int LAYER, int BLK, int UNR>
__global__ void __launch_bounds__(BLK) attn_kernel() {
    constexpr int F  = (LAYER == 1) ? HID : OUT_DIM;
    constexpr int NS = (LAYER == 1) ? S1 : S2;
    constexpr int TJ = 64;
    constexpr int NH = (LAYER == 1) ? NHEAD : 1;
    const float* Vall = (LAYER == 1) ? g_h1 : g_h2;
    const float* srcv = (LAYER == 1) ? g_src1 : g_src2;
    const float* dstv = (LAYER == 1) ? g_dst1 : g_dst2;
    const float* gm   = (LAYER == 1) ? g_gm1 : g_gm2;
    float* part = (LAYER == 1) ? g_part1 : g_part2;
    float* lout = (LAYER == 1) ? g_l1 : g_l2;

    __shared__ __align__(16) float sV[TJ * F];
    __shared__ float sD[TJ];

    int h = blockIdx.y, s = blockIdx.z;
    int i = blockIdx.x * BLK + threadIdx.x;
    const float* V = Vall + (size_t)h * NN * F;
    float srci = srcv[h * NN + i];
    float mi = lrelu(srci + gm[h]);

    float4 acc[F / 4];
#pragma unroll
    for (int f = 0; f < F / 4; f++) acc[f] = make_float4(0.f, 0.f, 0.f, 0.f);
    float l = 0.f;

    const int jspan = NN / NS;
    const int j0 = s * jspan;
    for (int jt = j0; jt < j0 + jspan; jt += TJ) {
        __syncthreads();
        const float4* gv = (const float4*)(V + (size_t)jt * F);
        float4* sv4 = (float4*)sV;
        for (int t = threadIdx.x; t < TJ * F / 4; t += BLK) sv4[t] = gv[t];
        if (threadIdx.x < TJ) sD[threadIdx.x] = dstv[h * NN + jt + threadIdx.x];
        __syncthreads();

        unsigned long long bits =
            (unsigned long long)g_adjT[(size_t)(jt >> 5) * NN + i] |
            ((unsigned long long)g_adjT[(size_t)((jt >> 5) + 1) * NN + i] << 32);

#pragma unroll UNR
        for (int jj = 0; jj < TJ; jj++) {
            float p = 0.f;
            if ((bits >> jj) & 1ull) p = __expf(lrelu(srci + sD[jj]) - mi);
            l += p;
            const float4* vr = (const float4*)(sV + jj * F);
#pragma unroll
            for (int f = 0; f < F / 4; f++) {
                float4 v = vr[f];
                acc[f].x = fmaf(p, v.x, acc[f].x);
                acc[f].y = fmaf(p, v.y, acc[f].y);
                acc[f].z = fmaf(p, v.z, acc[f].z);
                acc[f].w = fmaf(p, v.w, acc[f].w);
            }
        }
    }

    float4* po = (float4*)(part + (((size_t)s * NH + h) * NN + i) * F);
#pragma unroll
    for (int f = 0; f < F / 4; f++) po[f] = acc[f];
    lout[((size_t)s * NH + h) * NN + i] = l;
}

// ---------------------------------------------------------------------------
// 6) Reduce splits, divide by l, (layer 1: ELU), write to hcat / output.
// ---------------------------------------------------------------------------
template <int LAYER>
__global__ void finalize_kernel(float* __restrict__ outp) {
    constexpr int F  = (LAYER == 1) ? HID : OUT_DIM;
    constexpr int NS = (LAYER == 1) ? S1 : S2;
    constexpr int NH = (LAYER == 1) ? NHEAD : 1;
    const float* part = (LAYER == 1) ? g_part1 : g_part2;
    const float* lsum = (LAYER == 1) ? g_l1 : g_l2;

    int idx = blockIdx.x * 256 + threadIdx.x;
    int f = idx % F;
    int i = (idx / F) % NN;
    int h = idx / (F * NN);
    float a = 0.f, L = 0.f;
#pragma unroll
    for (int s = 0; s < NS; s++) {
        a += part[(((size_t)s * NH + h) * NN + i) * F + f];
        L += lsum[((size_t)s * NH + h) * NN + i];
    }
    float v = a / L;
    if (LAYER == 1) {
        v = v > 0.f ? v : expm1f(v);
        g_hcat[(size_t)i * (NHEAD * HID) + h * HID + f] = v;
    } else {
        outp[(size_t)i * OUT_DIM + f] = v;
    }
}

// ---------------------------------------------------------------------------
extern "C" void kernel_launch(void* const* d_in, const int* in_sizes, int n_in,
                              void* d_out, int out_size) {
    const float* x   = (const float*)d_in[0];   // [4096,256]
    const int*   adj = (const int*)d_in[1];     // [4096,4096]
    const float* W1  = (const float*)d_in[2];   // [4,256,64]
    const float* a1  = (const float*)d_in[3];   // [4,128]
    const float* W2  = (const float*)d_in[4];   // [256,128]
    const float* a2  = (const float*)d_in[5];   // [256]
    float* out = (float*)d_out;                 // [4096,128]

    pack_adj_kernel<<<(size_t)NN * NW / 8, 256>>>(adj);

    // ---- layer 1 ----
    gemm_kernel<1><<<dim3(1, NN / 64, NHEAD), 256>>>(x, W1);
    srcdst_kernel<1><<<dim3(NN / 8, NHEAD), 256>>>(a1);
    gmax_kernel<1><<<NHEAD, 256>>>();
    attn_kernel<1, 256, 4><<<dim3(NN / 256, NHEAD, S1), 256>>>();
    finalize_kernel<1><<<NHEAD * NN * HID / 256, 256>>>(nullptr);

    // ---- layer 2 ----
    gemm_kernel<2><<<dim3(OUT_DIM / 64, NN / 64, 1), 256>>>(nullptr, W2);
    srcdst_kernel<2><<<dim3(NN / 8, 1), 256>>>(a2);
    gmax_kernel<2><<<1, 256>>>();
    attn_kernel<2, 128, 2><<<dim3(NN / 128, 1, S2), 128>>>();
    finalize_kernel<2><<<NN * OUT_DIM / 256, 256>>>(out);
}

// round 11
// speedup vs baseline: 1.6167x; 1.0340x over previous
#include <cuda_runtime.h>
#include <cstdint>
#include <cstddef>

#define NN 4096
#define IN_DIM 256
#define HID 64
#define OUT_DIM 128
#define NHEAD 4
#define NW 128          // bitmask words per row
#define S1 8            // layer-1 j-splits -> 16*4*8 = 512 CTAs
#define S2 16           // layer-2 j-splits -> 16*2*16 = 512 CTAs

// ----------------- scratch globals (no allocation allowed) ------------------
__device__ uint32_t g_adjT[(size_t)NW * NN];                   // 2 MB
__device__ float g_h1[(size_t)NHEAD * NN * HID];               // [h][n][64]
__device__ float g_src1[NHEAD * NN], g_dst1[NHEAD * NN];
__device__ float g_gm1[NHEAD], g_gm2[1];
__device__ float g_hcat[(size_t)NN * (NHEAD * HID)];
__device__ float g_h2[(size_t)NN * OUT_DIM];                   // [n][128]
__device__ float g_src2[NN], g_dst2[NN];
__device__ float g_part1[(size_t)S1 * NHEAD * NN * HID];       // 32 MB
__device__ float g_l1[S1 * NHEAD * NN];
__device__ float g_part2[(size_t)S2 * NN * OUT_DIM];           // 32 MB
__device__ float g_l2[S2 * NN];

// ----------------------------- helpers --------------------------------------
__device__ __forceinline__ float lrelu(float x) { return fmaxf(x, 0.2f * x); }

// packed fp32x2 FMA (sm_100 base ISA): d = a*b + d per 32-bit half
__device__ __forceinline__ void fma2(unsigned long long& d,
                                     unsigned long long a, unsigned long long b) {
    asm("fma.rn.f32x2 %0, %1, %2, %0;" : "+l"(d) : "l"(a), "l"(b));
}
__device__ __forceinline__ unsigned long long pk2(float x) {
    unsigned long long r;
    asm("mov.b64 %0, {%1, %1};" : "=l"(r) : "f"(x));
    return r;
}

// ---------------------------------------------------------------------------
// 1) pack adjacency -> transposed bitmask
// ---------------------------------------------------------------------------
__global__ void pack_adj_kernel(const int* __restrict__ adj) {
    int gw   = (blockIdx.x * blockDim.x + threadIdx.x) >> 5;
    int lane = threadIdx.x & 31;
    int row = gw >> 7;
    int w   = gw & (NW - 1);
    int v = adj[(size_t)row * NN + (w << 5) + lane];
    unsigned m = __ballot_sync(0xffffffffu, v > 0);
    if (lane == 0) g_adjT[(size_t)w * NN + row] = m;
}

// ---------------------------------------------------------------------------
// 2) projection GEMM (fp32, 64x64 tiles)
// ---------------------------------------------------------------------------
template <int LAYER>
__global__ void __launch_bounds__(256) gemm_kernel(const float* __restrict__ Ain,
                                                   const float* __restrict__ Bin) {
    constexpr int K  = IN_DIM;
    constexpr int Nc = (LAYER == 1) ? HID : OUT_DIM;
    const float* A = (LAYER == 1) ? Ain : g_hcat;
    const float* B = Bin + (size_t)blockIdx.z * ((LAYER == 1) ? (size_t)IN_DIM * HID : 0);
    float* C = ((LAYER == 1) ? g_h1 : g_h2) + (size_t)blockIdx.z * NN * HID;

    __shared__ float As[16][66];
    __shared__ float Bs[16][64];

    int row0 = blockIdx.y * 64, col0 = blockIdx.x * 64;
    int tx = threadIdx.x & 15, ty = threadIdx.x >> 4;
    float acc[4][4] = {};

    for (int k0 = 0; k0 < K; k0 += 16) {
        for (int t = threadIdx.x; t < 64 * 16; t += 256) {
            int r = t >> 4, c = t & 15;
            As[c][r] = A[(size_t)(row0 + r) * K + k0 + c];
        }
        for (int t = threadIdx.x; t < 16 * 64; t += 256) {
            int r = t >> 6, c = t & 63;
            Bs[r][c] = B[(size_t)(k0 + r) * Nc + col0 + c];
        }
        __syncthreads();
#pragma unroll
        for (int kk = 0; kk < 16; kk++) {
            float av[4], bv[4];
#pragma unroll
            for (int u = 0; u < 4; u++) av[u] = As[kk][ty * 4 + u];
#pragma unroll
            for (int v = 0; v < 4; v++) bv[v] = Bs[kk][tx * 4 + v];
#pragma unroll
            for (int u = 0; u < 4; u++)
#pragma unroll
                for (int v = 0; v < 4; v++) acc[u][v] = fmaf(av[u], bv[v], acc[u][v]);
        }
        __syncthreads();
    }
#pragma unroll
    for (int u = 0; u < 4; u++)
#pragma unroll
        for (int v = 0; v < 4; v++)
            C[(size_t)(row0 + ty * 4 + u) * Nc + col0 + tx * 4 + v] = acc[u][v];
}

// ---------------------------------------------------------------------------
// 3) src/dst scalars. Warp per row.
// ---------------------------------------------------------------------------
template <int LAYER>
__global__ void srcdst_kernel(const float* __restrict__ avec) {
    constexpr int F = (LAYER == 1) ? HID : OUT_DIM;
    const float* feat = (LAYER == 1) ? g_h1 : g_h2;
    float* srcv = (LAYER == 1) ? g_src1 : g_src2;
    float* dstv = (LAYER == 1) ? g_dst1 : g_dst2;

    int h = blockIdx.y;
    int wid = threadIdx.x >> 5, lane = threadIdx.x & 31;
    int i = blockIdx.x * 8 + wid;
    const float* fr = feat + ((size_t)h * NN + i) * F;
    const float* a = avec + (size_t)h * 2 * F;
    float s = 0.f, d = 0.f;
#pragma unroll
    for (int c = lane; c < F; c += 32) {
        float v = fr[c];
        s = fmaf(v, a[c], s);
        d = fmaf(v, a[F + c], d);
    }
#pragma unroll
    for (int o = 16; o > 0; o >>= 1) {
        s += __shfl_xor_sync(0xffffffffu, s, o);
        d += __shfl_xor_sync(0xffffffffu, d, o);
    }
    if (lane == 0) { srcv[h * NN + i] = s; dstv[h * NN + i] = d; }
}

// ---------------------------------------------------------------------------
// 4) per-head global dst max (softmax shift bound; lrelu monotone)
// ---------------------------------------------------------------------------
template <int LAYER>
__global__ void gmax_kernel() {
    const float* dstv = (LAYER == 1) ? g_dst1 : g_dst2;
    float* gm = (LAYER == 1) ? g_gm1 : g_gm2;
    __shared__ float red[256];
    int h = blockIdx.x;
    float m = -3.0e38f;
    for (int t = threadIdx.x; t < NN; t += 256) m = fmaxf(m, dstv[h * NN + t]);
    red[threadIdx.x] = m;
    __syncthreads();
    for (int o = 128; o > 0; o >>= 1) {
        if (threadIdx.x < o) red[threadIdx.x] = fmaxf(red[threadIdx.x], red[threadIdx.x + o]);
        __syncthreads();
    }
    if (threadIdx.x == 0) gm[h] = red[0];
}

// ---------------------------------------------------------------------------
// 5) attention, scalar-exp + packed f32x2 FMA. 128 threads/CTA, 2 rows/thread
//    (256 rows/CTA), 64 features/thread. Layer 2 splits its 128 features
//    across blockIdx.y. j split across blockIdx.z; additive partials.
// ---------------------------------------------------------------------------
template <int LAYER>
__global__ void __launch_bounds__(128) attn_pk_kernel() {
    constexpr int TJ = 64;
    constexpr int NSpl = (LAYER == 1) ? S1 : S2;
    constexpr int Fall = (LAYER == 1) ? HID : OUT_DIM;   // V row stride

    __shared__ float sV[TJ * 64];    // 16 KB: TJ rows x 64-feature slice
    __shared__ float sD[TJ];

    int tid = threadIdx.x;
    int h  = (LAYER == 1) ? blockIdx.y : 0;
    int fb = (LAYER == 1) ? 0 : blockIdx.y * 64;
    int s  = blockIdx.z;
    int i0 = blockIdx.x * 256;
    int r0 = i0 + tid, r1 = r0 + 128;

    const float* Vsrc = (LAYER == 1) ? (g_h1 + (size_t)h * NN * HID) : g_h2;
    const float* srcv = (LAYER == 1) ? g_src1 : g_src2;
    const float* dstv = (LAYER == 1) ? g_dst1 : g_dst2;
    const float* gm   = (LAYER == 1) ? g_gm1 : g_gm2;

    float src0 = srcv[h * NN + r0];
    float src1 = srcv[h * NN + r1];
    float gmax = gm[h];
    float mi0 = lrelu(src0 + gmax);
    float mi1 = lrelu(src1 + gmax);

    unsigned long long acc0[32] = {};   // 64 feats as 32 f32x2
    unsigned long long acc1[32] = {};
    float ls0 = 0.f, ls1 = 0.f;

    const int j0 = s * (NN / NSpl);
    const int jend = j0 + NN / NSpl;
    for (int jt = j0; jt < jend; jt += TJ) {
        __syncthreads();
#pragma unroll
        for (int u = 0; u < 8; u++) {                     // stage TJ x 64 slice
            int idx = tid + u * 128;                      // 1024 float4 total
            int row = idx >> 4, fq = idx & 15;
            *(float4*)&sV[row * 64 + fq * 4] =
                *(const float4*)&Vsrc[(size_t)(jt + row) * Fall + fb + fq * 4];
        }
        if (tid < TJ) sD[tid] = dstv[h * NN + jt + tid];
        __syncthreads();

        int w = jt >> 5;
        unsigned long long bits0 = (unsigned long long)g_adjT[(size_t)w * NN + r0] |
                                   ((unsigned long long)g_adjT[(size_t)(w + 1) * NN + r0] << 32);
        unsigned long long bits1 = (unsigned long long)g_adjT[(size_t)w * NN + r1] |
                                   ((unsigned long long)g_adjT[(size_t)(w + 1) * NN + r1] << 32);

#pragma unroll 2
        for (int jj = 0; jj < TJ; jj++) {
            float d = sD[jj];
            float p0 = ((bits0 >> jj) & 1ull) ? __expf(lrelu(src0 + d) - mi0) : 0.f;
            float p1 = ((bits1 >> jj) & 1ull) ? __expf(lrelu(src1 + d) - mi1) : 0.f;
            ls0 += p0; ls1 += p1;
            unsigned long long P0 = pk2(p0), P1 = pk2(p1);
            const ulonglong2* vp = (const ulonglong2*)&sV[jj * 64];
#pragma unroll
            for (int fq = 0; fq < 16; fq++) {
                ulonglong2 v = vp[fq];
                fma2(acc0[2 * fq],     P0, v.x);
                fma2(acc0[2 * fq + 1], P0, v.y);
                fma2(acc1[2 * fq],     P1, v.x);
                fma2(acc1[2 * fq + 1], P1, v.y);
            }
        }
    }

    if (LAYER == 1) {
        float* p0 = g_part1 + (((size_t)(s * NHEAD + h) * NN) + r0) * HID;
        float* p1 = g_part1 + (((size_t)(s * NHEAD + h) * NN) + r1) * HID;
#pragma unroll
        for (int fq = 0; fq < 16; fq++) {
            *(ulonglong2*)&p0[fq * 4] = make_ulonglong2(acc0[2 * fq], acc0[2 * fq + 1]);
            *(ulonglong2*)&p1[fq * 4] = make_ulonglong2(acc1[2 * fq], acc1[2 * fq + 1]);
        }
        g_l1[(size_t)(s * NHEAD + h) * NN + r0] = ls0;
        g_l1[(size_t)(s * NHEAD + h) * NN + r1] = ls1;
    } else {
        float* p0 = g_part2 + ((size_t)s * NN + r0) * OUT_DIM + fb;
        float* p1 = g_part2 + ((size_t)s * NN + r1) * OUT_DIM + fb;
#pragma unroll
        for (int fq = 0; fq < 16; fq++) {
            *(ulonglong2*)&p0[fq * 4] = make_ulonglong2(acc0[2 * fq], acc0[2 * fq + 1]);
            *(ulonglong2*)&p1[fq * 4] = make_ulonglong2(acc1[2 * fq], acc1[2 * fq + 1]);
        }
        if (fb == 0) {
            g_l2[(size_t)s * NN + r0] = ls0;
            g_l2[(size_t)s * NN + r1] = ls1;
        }
    }
}

// ---------------------------------------------------------------------------
// 6) finalize layer 1: sum splits, divide, ELU, write hcat
// ---------------------------------------------------------------------------
__global__ void finalize1_kernel() {
    int idx = blockIdx.x * 256 + threadIdx.x;      // NHEAD*NN*HID
    int f = idx & (HID - 1);
    int i = (idx >> 6) & (NN - 1);
    int h = idx >> 18;
    float a = 0.f, L = 0.f;
#pragma unroll
    for (int s = 0; s < S1; s++) {
        a += g_part1[(((size_t)(s * NHEAD + h) * NN) + i) * HID + f];
        L += g_l1[(size_t)(s * NHEAD + h) * NN + i];
    }
    float v = a / L;
    v = v > 0.f ? v : expm1f(v);
    g_hcat[(size_t)i * (NHEAD * HID) + h * HID + f] = v;
}

// ---------------------------------------------------------------------------
// 7) finalize layer 2: sum splits, divide
// ---------------------------------------------------------------------------
__global__ void finalize2_kernel(float* __restrict__ outp) {
    int idx = blockIdx.x * 256 + threadIdx.x;      // NN*128
    int f = idx & (OUT_DIM - 1);
    int i = idx >> 7;
    float a = 0.f, L = 0.f;
#pragma unroll
    for (int s = 0; s < S2; s++) {
        a += g_part2[((size_t)s * NN + i) * OUT_DIM + f];
        L += g_l2[(size_t)s * NN + i];
    }
    outp[idx] = a / L;
}

// ---------------------------------------------------------------------------
extern "C" void kernel_launch(void* const* d_in, const int* in_sizes, int n_in,
                              void* d_out, int out_size) {
    const float* x   = (const float*)d_in[0];
    const int*   adj = (const int*)d_in[1];
    const float* W1  = (const float*)d_in[2];
    const float* a1  = (const float*)d_in[3];
    const float* W2  = (const float*)d_in[4];
    const float* a2  = (const float*)d_in[5];
    float* out = (float*)d_out;

    pack_adj_kernel<<<(size_t)NN * NW / 8, 256>>>(adj);

    // ---- layer 1 ----
    gemm_kernel<1><<<dim3(1, NN / 64, NHEAD), 256>>>(x, W1);
    srcdst_kernel<1><<<dim3(NN / 8, NHEAD), 256>>>(a1);
    gmax_kernel<1><<<NHEAD, 256>>>();
    attn_pk_kernel<1><<<dim3(NN / 256, NHEAD, S1), 128>>>();
    finalize1_kernel<<<NHEAD * NN * HID / 256, 256>>>();

    // ---- layer 2 ----
    gemm_kernel<2><<<dim3(OUT_DIM / 64, NN / 64, 1), 256>>>(nullptr, W2);
    srcdst_kernel<2><<<dim3(NN / 8, 1), 256>>>(a2);
    gmax_kernel<2><<<1, 256>>>();
    attn_pk_kernel<2><<<dim3(NN / 256, 2, S2), 128>>>();
    finalize2_kernel<<<NN * OUT_DIM / 256, 256>>>(out);
}

// round 12
// speedup vs baseline: 1.7968x; 1.1114x over previous
#include <cuda_runtime.h>
#include <cstdint>
#include <cstddef>

#define NN 4096
#define IN_DIM 256
#define HID 64
#define OUT_DIM 128
#define NHEAD 4
#define NW 128          // bitmask words per row
#define S1 8            // layer-1 j-splits -> 16*8*8  = 1024 CTAs
#define S2 16           // layer-2 j-splits -> 16*4*16 = 1024 CTAs

// ----------------- scratch globals (no allocation allowed) ------------------
__device__ uint32_t g_adjT[(size_t)NW * NN];                   // 2 MB
__device__ float g_h1[(size_t)NHEAD * NN * HID];               // [h][n][64]
__device__ float g_src1[NHEAD * NN], g_dst1[NHEAD * NN];
__device__ float g_gm1[NHEAD], g_gm2[1];
__device__ float g_hcat[(size_t)NN * (NHEAD * HID)];
__device__ float g_h2[(size_t)NN * OUT_DIM];                   // [n][128]
__device__ float g_src2[NN], g_dst2[NN];
__device__ float g_part1[(size_t)S1 * NHEAD * NN * HID];       // 32 MB
__device__ float g_l1[S1 * NHEAD * NN];
__device__ float g_part2[(size_t)S2 * NN * OUT_DIM];           // 32 MB
__device__ float g_l2[S2 * NN];

// ----------------------------- helpers --------------------------------------
__device__ __forceinline__ float lrelu(float x) { return fmaxf(x, 0.2f * x); }

// ---------------------------------------------------------------------------
// 1) pack adjacency -> transposed bitmask
// ---------------------------------------------------------------------------
__global__ void pack_adj_kernel(const int* __restrict__ adj) {
    int gw   = (blockIdx.x * blockDim.x + threadIdx.x) >> 5;
    int lane = threadIdx.x & 31;
    int row = gw >> 7;
    int w   = gw & (NW - 1);
    int v = adj[(size_t)row * NN + (w << 5) + lane];
    unsigned m = __ballot_sync(0xffffffffu, v > 0);
    if (lane == 0) g_adjT[(size_t)w * NN + row] = m;
}

// ---------------------------------------------------------------------------
// 2) projection GEMM (fp32, 64x64 tiles)
// ---------------------------------------------------------------------------
template <int LAYER>
__global__ void __launch_bounds__(256) gemm_kernel(const float* __restrict__ Ain,
                                                   const float* __restrict__ Bin) {
    constexpr int K  = IN_DIM;
    constexpr int Nc = (LAYER == 1) ? HID : OUT_DIM;
    const float* A = (LAYER == 1) ? Ain : g_hcat;
    const float* B = Bin + (size_t)blockIdx.z * ((LAYER == 1) ? (size_t)IN_DIM * HID : 0);
    float* C = ((LAYER == 1) ? g_h1 : g_h2) + (size_t)blockIdx.z * NN * HID;

    __shared__ float As[16][66];
    __shared__ float Bs[16][64];

    int row0 = blockIdx.y * 64, col0 = blockIdx.x * 64;
    int tx = threadIdx.x & 15, ty = threadIdx.x >> 4;
    float acc[4][4] = {};

    for (int k0 = 0; k0 < K; k0 += 16) {
        for (int t = threadIdx.x; t < 64 * 16; t += 256) {
            int r = t >> 4, c = t & 15;
            As[c][r] = A[(size_t)(row0 + r) * K + k0 + c];
        }
        for (int t = threadIdx.x; t < 16 * 64; t += 256) {
            int r = t >> 6, c = t & 63;
            Bs[r][c] = B[(size_t)(k0 + r) * Nc + col0 + c];
        }
        __syncthreads();
#pragma unroll
        for (int kk = 0; kk < 16; kk++) {
            float av[4], bv[4];
#pragma unroll
            for (int u = 0; u < 4; u++) av[u] = As[kk][ty * 4 + u];
#pragma unroll
            for (int v = 0; v < 4; v++) bv[v] = Bs[kk][tx * 4 + v];
#pragma unroll
            for (int u = 0; u < 4; u++)
#pragma unroll
                for (int v = 0; v < 4; v++) acc[u][v] = fmaf(av[u], bv[v], acc[u][v]);
        }
        __syncthreads();
    }
#pragma unroll
    for (int u = 0; u < 4; u++)
#pragma unroll
        for (int v = 0; v < 4; v++)
            C[(size_t)(row0 + ty * 4 + u) * Nc + col0 + tx * 4 + v] = acc[u][v];
}

// ---------------------------------------------------------------------------
// 3) src/dst scalars. Warp per row.
// ---------------------------------------------------------------------------
template <int LAYER>
__global__ void srcdst_kernel(const float* __restrict__ avec) {
    constexpr int F = (LAYER == 1) ? HID : OUT_DIM;
    const float* feat = (LAYER == 1) ? g_h1 : g_h2;
    float* srcv = (LAYER == 1) ? g_src1 : g_src2;
    float* dstv = (LAYER == 1) ? g_dst1 : g_dst2;

    int h = blockIdx.y;
    int wid = threadIdx.x >> 5, lane = threadIdx.x & 31;
    int i = blockIdx.x * 8 + wid;
    const float* fr = feat + ((size_t)h * NN + i) * F;
    const float* a = avec + (size_t)h * 2 * F;
    float s = 0.f, d = 0.f;
#pragma unroll
    for (int c = lane; c < F; c += 32) {
        float v = fr[c];
        s = fmaf(v, a[c], s);
        d = fmaf(v, a[F + c], d);
    }
#pragma unroll
    for (int o = 16; o > 0; o >>= 1) {
        s += __shfl_xor_sync(0xffffffffu, s, o);
        d += __shfl_xor_sync(0xffffffffu, d, o);
    }
    if (lane == 0) { srcv[h * NN + i] = s; dstv[h * NN + i] = d; }
}

// ---------------------------------------------------------------------------
// 4) per-head global dst max (softmax shift bound; lrelu monotone)
// ---------------------------------------------------------------------------
template <int LAYER>
__global__ void gmax_kernel() {
    const float* dstv = (LAYER == 1) ? g_dst1 : g_dst2;
    float* gm = (LAYER == 1) ? g_gm1 : g_gm2;
    __shared__ float red[256];
    int h = blockIdx.x;
    float m = -3.0e38f;
    for (int t = threadIdx.x; t < NN; t += 256) m = fmaxf(m, dstv[h * NN + t]);
    red[threadIdx.x] = m;
    __syncthreads();
    for (int o = 128; o > 0; o >>= 1) {
        if (threadIdx.x < o) red[threadIdx.x] = fmaxf(red[threadIdx.x], red[threadIdx.x + o]);
        __syncthreads();
    }
    if (threadIdx.x == 0) gm[h] = red[0];
}

// ---------------------------------------------------------------------------
// 5) attention: scalar FFMA, 2 rows x 32 features per thread, 128 thr/CTA
//    (256 rows/CTA). Feature slices over blockIdx.y (L1: head*2+slice,
//    L2: 4 slices). j split over blockIdx.z; additive partials.
// ---------------------------------------------------------------------------
template <int LAYER>
__global__ void __launch_bounds__(128) attn_kernel() {
    constexpr int TJ = 64;
    constexpr int NSpl = (LAYER == 1) ? S1 : S2;
    constexpr int Fall = (LAYER == 1) ? HID : OUT_DIM;   // V row stride
    constexpr int FSUB = 32;

    __shared__ float sV[TJ * FSUB];   // 8 KB
    __shared__ float sD[TJ];

    int tid = threadIdx.x;
    int h  = (LAYER == 1) ? (blockIdx.y >> 1) : 0;
    int fb = (LAYER == 1) ? ((blockIdx.y & 1) * FSUB) : (blockIdx.y * FSUB);
    int s  = blockIdx.z;
    int i0 = blockIdx.x * 256;
    int r0 = i0 + tid, r1 = r0 + 128;

    const float* Vsrc = (LAYER == 1) ? (g_h1 + (size_t)h * NN * HID) : g_h2;
    const float* srcv = (LAYER == 1) ? g_src1 : g_src2;
    const float* dstv = (LAYER == 1) ? g_dst1 : g_dst2;
    const float* gm   = (LAYER == 1) ? g_gm1 : g_gm2;

    float src0 = srcv[h * NN + r0];
    float src1 = srcv[h * NN + r1];
    float gmax = gm[h];
    float mi0 = lrelu(src0 + gmax);
    float mi1 = lrelu(src1 + gmax);

    float4 a0[8], a1[8];
#pragma unroll
    for (int u = 0; u < 8; u++) { a0[u] = make_float4(0.f, 0.f, 0.f, 0.f); a1[u] = a0[u]; }
    float ls0 = 0.f, ls1 = 0.f;

    const int j0 = s * (NN / NSpl);
    const int jend = j0 + NN / NSpl;
    for (int jt = j0; jt < jend; jt += TJ) {
        __syncthreads();
#pragma unroll
        for (int u = 0; u < 4; u++) {                     // 512 float4 total
            int idx = tid + u * 128;
            int row = idx >> 3, fq = idx & 7;
            *(float4*)&sV[row * FSUB + fq * 4] =
                *(const float4*)&Vsrc[(size_t)(jt + row) * Fall + fb + fq * 4];
        }
        if (tid < TJ) sD[tid] = dstv[h * NN + jt + tid];
        __syncthreads();

        int w = jt >> 5;
        unsigned long long bits0 = (unsigned long long)g_adjT[(size_t)w * NN + r0] |
                                   ((unsigned long long)g_adjT[(size_t)(w + 1) * NN + r0] << 32);
        unsigned long long bits1 = (unsigned long long)g_adjT[(size_t)w * NN + r1] |
                                   ((unsigned long long)g_adjT[(size_t)(w + 1) * NN + r1] << 32);

#pragma unroll 2
        for (int jj = 0; jj < TJ; jj++) {
            float d = sD[jj];
            float p0 = ((bits0 >> jj) & 1ull) ? __expf(lrelu(src0 + d) - mi0) : 0.f;
            float p1 = ((bits1 >> jj) & 1ull) ? __expf(lrelu(src1 + d) - mi1) : 0.f;
            ls0 += p0; ls1 += p1;
            const float4* vp = (const float4*)&sV[jj * FSUB];
#pragma unroll
            for (int fq = 0; fq < 8; fq++) {
                float4 v = vp[fq];
                a0[fq].x = fmaf(p0, v.x, a0[fq].x);
                a0[fq].y = fmaf(p0, v.y, a0[fq].y);
                a0[fq].z = fmaf(p0, v.z, a0[fq].z);
                a0[fq].w = fmaf(p0, v.w, a0[fq].w);
                a1[fq].x = fmaf(p1, v.x, a1[fq].x);
                a1[fq].y = fmaf(p1, v.y, a1[fq].y);
                a1[fq].z = fmaf(p1, v.z, a1[fq].z);
                a1[fq].w = fmaf(p1, v.w, a1[fq].w);
            }
        }
    }

    if (LAYER == 1) {
        float* p0 = g_part1 + (((size_t)(s * NHEAD + h) * NN) + r0) * HID + fb;
        float* p1 = g_part1 + (((size_t)(s * NHEAD + h) * NN) + r1) * HID + fb;
#pragma unroll
        for (int fq = 0; fq < 8; fq++) {
            *(float4*)&p0[fq * 4] = a0[fq];
            *(float4*)&p1[fq * 4] = a1[fq];
        }
        if (fb == 0) {
            g_l1[(size_t)(s * NHEAD + h) * NN + r0] = ls0;
            g_l1[(size_t)(s * NHEAD + h) * NN + r1] = ls1;
        }
    } else {
        float* p0 = g_part2 + ((size_t)s * NN + r0) * OUT_DIM + fb;
        float* p1 = g_part2 + ((size_t)s * NN + r1) * OUT_DIM + fb;
#pragma unroll
        for (int fq = 0; fq < 8; fq++) {
            *(float4*)&p0[fq * 4] = a0[fq];
            *(float4*)&p1[fq * 4] = a1[fq];
        }
        if (fb == 0) {
            g_l2[(size_t)s * NN + r0] = ls0;
            g_l2[(size_t)s * NN + r1] = ls1;
        }
    }
}

// ---------------------------------------------------------------------------
// 6) finalize layer 1: sum splits, divide, ELU, write hcat
// ---------------------------------------------------------------------------
__global__ void finalize1_kernel() {
    int idx = blockIdx.x * 256 + threadIdx.x;      // NHEAD*NN*HID
    int f = idx & (HID - 1);
    int i = (idx >> 6) & (NN - 1);
    int h = idx >> 18;
    float a = 0.f, L = 0.f;
#pragma unroll
    for (int s = 0; s < S1; s++) {
        a += g_part1[(((size_t)(s * NHEAD + h) * NN) + i) * HID + f];
        L += g_l1[(size_t)(s * NHEAD + h) * NN + i];
    }
    float v = a / L;
    v = v > 0.f ? v : expm1f(v);
    g_hcat[(size_t)i * (NHEAD * HID) + h * HID + f] = v;
}

// ---------------------------------------------------------------------------
// 7) finalize layer 2: sum splits, divide
// ---------------------------------------------------------------------------
__global__ void finalize2_kernel(float* __restrict__ outp) {
    int idx = blockIdx.x * 256 + threadIdx.x;      // NN*128
    int f = idx & (OUT_DIM - 1);
    int i = idx >> 7;
    float a = 0.f, L = 0.f;
#pragma unroll
    for (int s = 0; s < S2; s++) {
        a += g_part2[((size_t)s * NN + i) * OUT_DIM + f];
        L += g_l2[(size_t)s * NN + i];
    }
    outp[idx] = a / L;
}

// ---------------------------------------------------------------------------
extern "C" void kernel_launch(void* const* d_in, const int* in_sizes, int n_in,
                              void* d_out, int out_size) {
    const float* x   = (const float*)d_in[0];
    const int*   adj = (const int*)d_in[1];
    const float* W1  = (const float*)d_in[2];
    const float* a1  = (const float*)d_in[3];
    const float* W2  = (const float*)d_in[4];
    const float* a2  = (const float*)d_in[5];
    float* out = (float*)d_out;

    pack_adj_kernel<<<(size_t)NN * NW / 8, 256>>>(adj);

    // ---- layer 1 ----
    gemm_kernel<1><<<dim3(1, NN / 64, NHEAD), 256>>>(x, W1);
    srcdst_kernel<1><<<dim3(NN / 8, NHEAD), 256>>>(a1);
    gmax_kernel<1><<<NHEAD, 256>>>();
    attn_kernel<1><<<dim3(NN / 256, NHEAD * 2, S1), 128>>>();
    finalize1_kernel<<<NHEAD * NN * HID / 256, 256>>>();

    // ---- layer 2 ----
    gemm_kernel<2><<<dim3(OUT_DIM / 64, NN / 64, 1), 256>>>(nullptr, W2);
    srcdst_kernel<2><<<dim3(NN / 8, 1), 256>>>(a2);
    gmax_kernel<2><<<1, 256>>>();
    attn_kernel<2><<<dim3(NN / 256, OUT_DIM / 32, S2), 128>>>();
    finalize2_kernel<<<NN * OUT_DIM / 256, 256>>>(out);
}

// round 15
// speedup vs baseline: 2.1602x; 1.2023x over previous
#include <cuda_runtime.h>
#include <cstdint>
#include <cstddef>

#define NN 4096
#define IN_DIM 256
#define HID 64
#define OUT_DIM 128
#define NHEAD 4
#define NW 128          // bitmask words per row
#define S1 16           // layer-1 j-splits -> 16*8*16 = 2048 CTAs
#define S2 32           // layer-2 j-splits -> 16*4*32 = 2048 CTAs

// ----------------- scratch globals (no allocation allowed) ------------------
__device__ uint32_t g_adjT[(size_t)NW * NN];                   // 2 MB
__device__ float g_h1[(size_t)NHEAD * NN * HID];               // [h][n][64]
__device__ float g_src1[NHEAD * NN], g_dst1[NHEAD * NN];
__device__ unsigned g_gmU1[NHEAD], g_gmU2[1];                  // ordered-uint dst max
__device__ float2 g_E12[NHEAD * NN], g_F12[NHEAD * NN];        // factored exps
__device__ float g_hcat[(size_t)NN * (NHEAD * HID)];
__device__ float g_h2[(size_t)NN * OUT_DIM];                   // [n][128]
__device__ float g_src2[NN], g_dst2[NN];
__device__ float g_part1[(size_t)S1 * NHEAD * NN * HID];       // 64 MB
__device__ float g_l1[S1 * NHEAD * NN];
__device__ float g_part2[(size_t)S2 * NN * OUT_DIM];           // 64 MB
__device__ float g_l2[S2 * NN];

// ----------------------------- helpers --------------------------------------
__device__ __forceinline__ float lrelu(float x) { return fmaxf(x, 0.2f * x); }
__device__ __forceinline__ unsigned umap(float x) {
    unsigned u = __float_as_uint(x);
    return (u & 0x80000000u) ? ~u : (u | 0x80000000u);
}
__device__ __forceinline__ float uunmap(unsigned v) {
    return (v & 0x80000000u) ? __uint_as_float(v & 0x7fffffffu)
                             : __uint_as_float(~v);
}

// ---------------------------------------------------------------------------
// 1) pack adjacency -> transposed bitmask; init gmax accumulators
// ---------------------------------------------------------------------------
__global__ void pack_adj_kernel(const int* __restrict__ adj) {
    if (blockIdx.x == 0) {
        if (threadIdx.x < NHEAD) g_gmU1[threadIdx.x] = 0u;
        if (threadIdx.x == NHEAD) g_gmU2[0] = 0u;
    }
    int gw   = (blockIdx.x * blockDim.x + threadIdx.x) >> 5;
    int lane = threadIdx.x & 31;
    int row = gw >> 7;
    int w   = gw & (NW - 1);
    int v = adj[(size_t)row * NN + (w << 5) + lane];
    unsigned m = __ballot_sync(0xffffffffu, v > 0);
    if (lane == 0) g_adjT[(size_t)w * NN + row] = m;
}

// ---------------------------------------------------------------------------
// 2) projection GEMM (fp32, 64x64 tiles)   [proven]
// ---------------------------------------------------------------------------
template <int LAYER>
__global__ void __launch_bounds__(256) gemm_kernel(const float* __restrict__ Ain,
                                                   const float* __restrict__ Bin) {
    constexpr int K  = IN_DIM;
    constexpr int Nc = (LAYER == 1) ? HID : OUT_DIM;
    const float* A = (LAYER == 1) ? Ain : g_hcat;
    const float* B = Bin + (size_t)blockIdx.z * ((LAYER == 1) ? (size_t)IN_DIM * HID : 0);
    float* C = ((LAYER == 1) ? g_h1 : g_h2) + (size_t)blockIdx.z * NN * HID;

    __shared__ float As[16][66];
    __shared__ float Bs[16][64];

    int row0 = blockIdx.y * 64, col0 = blockIdx.x * 64;
    int tx = threadIdx.x & 15, ty = threadIdx.x >> 4;
    float acc[4][4] = {};

    for (int k0 = 0; k0 < K; k0 += 16) {
        for (int t = threadIdx.x; t < 64 * 16; t += 256) {
            int r = t >> 4, c = t & 15;
            As[c][r] = A[(size_t)(row0 + r) * K + k0 + c];
        }
        for (int t = threadIdx.x; t < 16 * 64; t += 256) {
            int r = t >> 6, c = t & 63;
            Bs[r][c] = B[(size_t)(k0 + r) * Nc + col0 + c];
        }
        __syncthreads();
#pragma unroll
        for (int kk = 0; kk < 16; kk++) {
            float av[4], bv[4];
#pragma unroll
            for (int u = 0; u < 4; u++) av[u] = As[kk][ty * 4 + u];
#pragma unroll
            for (int v = 0; v < 4; v++) bv[v] = Bs[kk][tx * 4 + v];
#pragma unroll
            for (int u = 0; u < 4; u++)
#pragma unroll
                for (int v = 0; v < 4; v++) acc[u][v] = fmaf(av[u], bv[v], acc[u][v]);
        }
        __syncthreads();
    }
#pragma unroll
    for (int u = 0; u < 4; u++)
#pragma unroll
        for (int v = 0; v < 4; v++)
            C[(size_t)(row0 + ty * 4 + u) * Nc + col0 + tx * 4 + v] = acc[u][v];
}

// ---------------------------------------------------------------------------
// 3) src/dst scalars + per-head global dst max (ordered-uint atomicMax)
// ---------------------------------------------------------------------------
template <int LAYER>
__global__ void srcdst_kernel(const float* __restrict__ avec) {
    constexpr int F = (LAYER == 1) ? HID : OUT_DIM;
    const float* feat = (LAYER == 1) ? g_h1 : g_h2;
    float* srcv = (LAYER == 1) ? g_src1 : g_src2;
    float* dstv = (LAYER == 1) ? g_dst1 : g_dst2;
    unsigned* gmU = (LAYER == 1) ? g_gmU1 : g_gmU2;

    __shared__ float sred[8];
    int h = blockIdx.y;
    int wid = threadIdx.x >> 5, lane = threadIdx.x & 31;
    int i = blockIdx.x * 8 + wid;
    const float* fr = feat + ((size_t)h * NN + i) * F;
    const float* a = avec + (size_t)h * 2 * F;
    float s = 0.f, d = 0.f;
#pragma unroll
    for (int c = lane; c < F; c += 32) {
        float v = fr[c];
        s = fmaf(v, a[c], s);
        d = fmaf(v, a[F + c], d);
    }
#pragma unroll
    for (int o = 16; o > 0; o >>= 1) {
        s += __shfl_xor_sync(0xffffffffu, s, o);
        d += __shfl_xor_sync(0xffffffffu, d, o);
    }
    if (lane == 0) { srcv[h * NN + i] = s; dstv[h * NN + i] = d; sred[wid] = d; }
    __syncthreads();
    if (threadIdx.x == 0) {
        float m = sred[0];
#pragma unroll
        for (int u = 1; u < 8; u++) m = fmaxf(m, sred[u]);
        atomicMax(&gmU[h], umap(m));
    }
}

// ---------------------------------------------------------------------------
// 4) prep: factored exponentials. p(i,j) = (src_i+dst_j>0) ? E1_i*F1_j
//    : E2_i*F2_j == exp(lrelu(src_i+dst_j) - mi). All factors <= 1.
// ---------------------------------------------------------------------------
template <int LAYER>
__global__ void prep_kernel() {
    const float* srcv = (LAYER == 1) ? g_src1 : g_src2;
    const float* dstv = (LAYER == 1) ? g_dst1 : g_dst2;
    const unsigned* gmU = (LAYER == 1) ? g_gmU1 : g_gmU2;
    int h = blockIdx.y;
    int i = blockIdx.x * 256 + threadIdx.x;
    float src = srcv[h * NN + i], dst = dstv[h * NN + i];
    float gx = uunmap(gmU[h]);
    float mi = lrelu(src + gx);
    g_E12[h * NN + i] = make_float2(__expf(src + gx - mi), __expf(0.2f * (src + gx) - mi));
    g_F12[h * NN + i] = make_float2(__expf(dst - gx), __expf(0.2f * (dst - gx)));
}

// ---------------------------------------------------------------------------
// 5) attention: scalar FFMA, factored p. 2 rows x 32 features per thread,
//    128 thr/CTA (256 rows/CTA). Feature slices over blockIdx.y; j split
//    over blockIdx.z (2048 CTAs/launch -> ~92% wave utilization).
// ---------------------------------------------------------------------------
template <int LAYER>
__global__ void __launch_bounds__(128) attn_kernel() {
    constexpr int TJ = 64;
    constexpr int NSpl = (LAYER == 1) ? S1 : S2;
    constexpr int Fall = (LAYER == 1) ? HID : OUT_DIM;   // V row stride
    constexpr int FSUB = 32;

    __shared__ float sV[TJ * FSUB];   // 8 KB
    __shared__ float sD[TJ];
    __shared__ float2 sF[TJ];

    int tid = threadIdx.x;
    int h  = (LAYER == 1) ? (blockIdx.y >> 1) : 0;
    int fb = (LAYER == 1) ? ((blockIdx.y & 1) * FSUB) : (blockIdx.y * FSUB);
    int s  = blockIdx.z;
    int i0 = blockIdx.x * 256;
    int r0 = i0 + tid, r1 = r0 + 128;

    const float* Vsrc = (LAYER == 1) ? (g_h1 + (size_t)h * NN * HID) : g_h2;
    const float* srcv = (LAYER == 1) ? g_src1 : g_src2;
    const float* dstv = (LAYER == 1) ? g_dst1 : g_dst2;

    float t0 = -srcv[h * NN + r0];
    float t1 = -srcv[h * NN + r1];
    float2 E0 = g_E12[h * NN + r0];
    float2 E1 = g_E12[h * NN + r1];

    float4 a0[8], a1[8];
#pragma unroll
    for (int u = 0; u < 8; u++) { a0[u] = make_float4(0.f, 0.f, 0.f, 0.f); a1[u] = a0[u]; }
    float ls0 = 0.f, ls1 = 0.f;

    const int j0 = s * (NN / NSpl);
    const int jend = j0 + NN / NSpl;
    for (int jt = j0; jt < jend; jt += TJ) {
        __syncthreads();
#pragma unroll
        for (int u = 0; u < 4; u++) {                     // 512 float4 total
            int idx = tid + u * 128;
            int row = idx >> 3, fq = idx & 7;
            *(float4*)&sV[row * FSUB + fq * 4] =
                *(const float4*)&Vsrc[(size_t)(jt + row) * Fall + fb + fq * 4];
        }
        if (tid < TJ) {
            sD[tid] = dstv[h * NN + jt + tid];
            sF[tid] = g_F12[h * NN + jt + tid];
        }
        __syncthreads();

        int w = jt >> 5;
        unsigned long long bits0 = (unsigned long long)g_adjT[(size_t)w * NN + r0] |
                                   ((unsigned long long)g_adjT[(size_t)(w + 1) * NN + r0] << 32);
        unsigned long long bits1 = (unsigned long long)g_adjT[(size_t)w * NN + r1] |
                                   ((unsigned long long)g_adjT[(size_t)(w + 1) * NN + r1] << 32);

#pragma unroll 2
        for (int jj = 0; jj < TJ; jj++) {
            float d = sD[jj];
            float2 f = sF[jj];
            float p0 = (d > t0) ? E0.x * f.x : E0.y * f.y;
            float p1 = (d > t1) ? E1.x * f.x : E1.y * f.y;
            p0 = ((bits0 >> jj) & 1ull) ? p0 : 0.f;
            p1 = ((bits1 >> jj) & 1ull) ? p1 : 0.f;
            ls0 += p0; ls1 += p1;
            const float4* vp = (const float4*)&sV[jj * FSUB];
#pragma unroll
            for (int fq = 0; fq < 8; fq++) {
                float4 v = vp[fq];
                a0[fq].x = fmaf(p0, v.x, a0[fq].x);
                a0[fq].y = fmaf(p0, v.y, a0[fq].y);
                a0[fq].z = fmaf(p0, v.z, a0[fq].z);
                a0[fq].w = fmaf(p0, v.w, a0[fq].w);
                a1[fq].x = fmaf(p1, v.x, a1[fq].x);
                a1[fq].y = fmaf(p1, v.y, a1[fq].y);
                a1[fq].z = fmaf(p1, v.z, a1[fq].z);
                a1[fq].w = fmaf(p1, v.w, a1[fq].w);
            }
        }
    }

    if (LAYER == 1) {
        float* p0 = g_part1 + (((size_t)(s * NHEAD + h) * NN) + r0) * HID + fb;
        float* p1 = g_part1 + (((size_t)(s * NHEAD + h) * NN) + r1) * HID + fb;
#pragma unroll
        for (int fq = 0; fq < 8; fq++) {
            *(float4*)&p0[fq * 4] = a0[fq];
            *(float4*)&p1[fq * 4] = a1[fq];
        }
        if (fb == 0) {
            g_l1[(size_t)(s * NHEAD + h) * NN + r0] = ls0;
            g_l1[(size_t)(s * NHEAD + h) * NN + r1] = ls1;
        }
    } else {
        float* p0 = g_part2 + ((size_t)s * NN + r0) * OUT_DIM + fb;
        float* p1 = g_part2 + ((size_t)s * NN + r1) * OUT_DIM + fb;
#pragma unroll
        for (int fq = 0; fq < 8; fq++) {
            *(float4*)&p0[fq * 4] = a0[fq];
            *(float4*)&p1[fq * 4] = a1[fq];
        }
        if (fb == 0) {
            g_l2[(size_t)s * NN + r0] = ls0;
            g_l2[(size_t)s * NN + r1] = ls1;
        }
    }
}

// ---------------------------------------------------------------------------
// 6) finalize layer 1: sum splits, divide, ELU, write hcat
// ---------------------------------------------------------------------------
__global__ void finalize1_kernel() {
    int idx = blockIdx.x * 256 + threadIdx.x;      // NHEAD*NN*HID
    int f = idx & (HID - 1);
    int i = (idx >> 6) & (NN - 1);
    int h = idx >> 18;
    float a = 0.f, L = 0.f;
#pragma unroll
    for (int s = 0; s < S1; s++) {
        a += g_part1[(((size_t)(s * NHEAD + h) * NN) + i) * HID + f];
        L += g_l1[(size_t)(s * NHEAD + h) * NN + i];
    }
    float v = a / L;
    v = v > 0.f ? v : expm1f(v);
    g_hcat[(size_t)i * (NHEAD * HID) + h * HID + f] = v;
}

// ---------------------------------------------------------------------------
// 7) finalize layer 2: sum splits, divide
// ---------------------------------------------------------------------------
__global__ void finalize2_kernel(float* __restrict__ outp) {
    int idx = blockIdx.x * 256 + threadIdx.x;      // NN*128
    int f = idx & (OUT_DIM - 1);
    int i = idx >> 7;
    float a = 0.f, L = 0.f;
#pragma unroll
    for (int s = 0; s < S2; s++) {
        a += g_part2[((size_t)s * NN + i) * OUT_DIM + f];
        L += g_l2[(size_t)s * NN + i];
    }
    outp[idx] = a / L;
}

// ---------------------------------------------------------------------------
extern "C" void kernel_launch(void* const* d_in, const int* in_sizes, int n_in,
                              void* d_out, int out_size) {
    const float* x   = (const float*)d_in[0];
    const int*   adj = (const int*)d_in[1];
    const float* W1  = (const float*)d_in[2];
    const float* a1  = (const float*)d_in[3];
    const float* W2  = (const float*)d_in[4];
    const float* a2  = (const float*)d_in[5];
    float* out = (float*)d_out;

    pack_adj_kernel<<<(size_t)NN * NW / 8, 256>>>(adj);

    // ---- layer 1 ----
    gemm_kernel<1><<<dim3(1, NN / 64, NHEAD), 256>>>(x, W1);
    srcdst_kernel<1><<<dim3(NN / 8, NHEAD), 256>>>(a1);
    prep_kernel<1><<<dim3(NN / 256, NHEAD), 256>>>();
    attn_kernel<1><<<dim3(NN / 256, NHEAD * 2, S1), 128>>>();
    finalize1_kernel<<<NHEAD * NN * HID / 256, 256>>>();

    // ---- layer 2 ----
    gemm_kernel<2><<<dim3(OUT_DIM / 64, NN / 64, 1), 256>>>(nullptr, W2);
    srcdst_kernel<2><<<dim3(NN / 8, 1), 256>>>(a2);
    prep_kernel<2><<<dim3(NN / 256, 1), 256>>>();
    attn_kernel<2><<<dim3(NN / 256, OUT_DIM / 32, S2), 128>>>();
    finalize2_kernel<<<NN * OUT_DIM / 256, 256>>>(out);
}